// round 13
// baseline (speedup 1.0000x reference)
#include <cuda_runtime.h>
#include <math_constants.h>

#define NFEAT 65536
#define FD    512
#define NC    256
#define RPC   (NFEAT / NC)      // 256 rows per class
#define F4D   (FD / 4)          // 128 float4 per row
#define RSPLIT 8                // row-chunks per class
#define RCHUNK (RPC / RSPLIT)   // 32 rows per chunk
#define NIT    32               // i-tiles (8 rows each)
#define NJT    8                // j-tiles (32 cols each)
#define NBLK2  (NIT * NJT)      // 256 sim blocks

// Scratch (no cudaMalloc allowed)
__device__ float g_partial[RSPLIT * NC * FD];  // 4 MB partial sums
__device__ float g_centers[NC * FD];           // normalized centers [j][k]
__device__ float g_centersT[FD * NC];          // normalized centers [k][j]
__device__ float g_partmin[NJT * NC];          // per-(jtile,row) partial min
__device__ unsigned int g_cnt[NC];             // per-class fan-in counters
__device__ unsigned int g_cnt2;                // sim fan-in counter

// ---------------------------------------------------------------------------
// Kernel 1: partial row-sums + per-class fan-in finalize.
// grid = 2048, block = 128. Block b: class c = b>>3, chunk s = b&7.
// The 8th block of each class folds the partials, applies mean + L2 norm,
// writes g_centers + g_centersT, resets the counter. Finalize work lands in
// ALU slots that are idle during the memory-bound main phase — cheaper than
// a separate kernel + boundary (R3 vs R9 ledger: ~2.5us cheaper).
// No spinning anywhere -> deadlock-free, replay-safe.
// ---------------------------------------------------------------------------
__global__ void __launch_bounds__(128) centers_kernel(const float* __restrict__ feat) {
    const int b = blockIdx.x;
    const int c = b >> 3;
    const int s = b & 7;
    const int t = threadIdx.x;

    const float4* __restrict__ p =
        reinterpret_cast<const float4*>(feat)
        + ((size_t)c * RPC + (size_t)s * RCHUNK) * F4D + t;

    float4 acc = make_float4(0.f, 0.f, 0.f, 0.f);
    #pragma unroll
    for (int r = 0; r < RCHUNK; ++r) {
        float4 v = __ldcs(p + (size_t)r * F4D);
        acc.x += v.x; acc.y += v.y; acc.z += v.z; acc.w += v.w;
    }
    reinterpret_cast<float4*>(g_partial)[((size_t)s * NC + c) * F4D + t] = acc;

    // fan-in: last of the 8 blocks for this class finalizes it
    __threadfence();
    __shared__ unsigned int s_prev;
    if (t == 0) s_prev = atomicAdd(&g_cnt[c], 1u);
    __syncthreads();
    if (s_prev != RSPLIT - 1) return;
    __threadfence();  // acquire: all partials for class c visible

    float4 sum = make_float4(0.f, 0.f, 0.f, 0.f);
    #pragma unroll
    for (int k = 0; k < RSPLIT; ++k) {
        float4 v = __ldcg(reinterpret_cast<const float4*>(g_partial)
                          + ((size_t)k * NC + c) * F4D + t);
        sum.x += v.x; sum.y += v.y; sum.z += v.z; sum.w += v.w;
    }
    const float inv = 1.0f / (float)RPC;
    sum.x *= inv; sum.y *= inv; sum.z *= inv; sum.w *= inv;

    float ss = sum.x*sum.x + sum.y*sum.y + sum.z*sum.z + sum.w*sum.w;
    #pragma unroll
    for (int o = 16; o > 0; o >>= 1)
        ss += __shfl_xor_sync(0xffffffffu, ss, o);

    __shared__ float sred[4];
    if ((t & 31) == 0) sred[t >> 5] = ss;
    __syncthreads();
    float total = sred[0] + sred[1] + sred[2] + sred[3];
    float invn = 1.0f / fmaxf(sqrtf(total), 1e-8f);

    float4 o4 = make_float4(sum.x * invn, sum.y * invn, sum.z * invn, sum.w * invn);
    reinterpret_cast<float4*>(g_centers)[(size_t)c * F4D + t] = o4;
    g_centersT[(size_t)(4 * t + 0) * NC + c] = o4.x;
    g_centersT[(size_t)(4 * t + 1) * NC + c] = o4.y;
    g_centersT[(size_t)(4 * t + 2) * NC + c] = o4.z;
    g_centersT[(size_t)(4 * t + 3) * NC + c] = o4.w;

    if (t == 0) g_cnt[c] = 0u;   // reset for next graph replay

#if __CUDA_ARCH__ >= 900
    cudaTriggerProgrammaticLaunchCompletion();
#endif
}

// ---------------------------------------------------------------------------
// Kernel 2: sim row mins, 8 i-rows x 32 j per block = 256 blocks (16 MB L2).
// PDL secondary: gates on K1 completion. Thread: jq = t&7 owns float4
// j-group, ks = t>>3 owns k in [16ks,16ks+16). 4 k-slices sharing a j-group
// fold intra-warp via shfl. Last block: min over j-tiles, sum(1-min)->out.
// ---------------------------------------------------------------------------
#define SIM_STEP8(A0, A1, A2, A3, A4, A5, A6, A7, V)                         \
    acc[0][0] += (A0)*(V).x; acc[0][1] += (A0)*(V).y;                        \
    acc[0][2] += (A0)*(V).z; acc[0][3] += (A0)*(V).w;                        \
    acc[1][0] += (A1)*(V).x; acc[1][1] += (A1)*(V).y;                        \
    acc[1][2] += (A1)*(V).z; acc[1][3] += (A1)*(V).w;                        \
    acc[2][0] += (A2)*(V).x; acc[2][1] += (A2)*(V).y;                        \
    acc[2][2] += (A2)*(V).z; acc[2][3] += (A2)*(V).w;                        \
    acc[3][0] += (A3)*(V).x; acc[3][1] += (A3)*(V).y;                        \
    acc[3][2] += (A3)*(V).z; acc[3][3] += (A3)*(V).w;                        \
    acc[4][0] += (A4)*(V).x; acc[4][1] += (A4)*(V).y;                        \
    acc[4][2] += (A4)*(V).z; acc[4][3] += (A4)*(V).w;                        \
    acc[5][0] += (A5)*(V).x; acc[5][1] += (A5)*(V).y;                        \
    acc[5][2] += (A5)*(V).z; acc[5][3] += (A5)*(V).w;                        \
    acc[6][0] += (A6)*(V).x; acc[6][1] += (A6)*(V).y;                        \
    acc[6][2] += (A6)*(V).z; acc[6][3] += (A6)*(V).w;                        \
    acc[7][0] += (A7)*(V).x; acc[7][1] += (A7)*(V).y;                        \
    acc[7][2] += (A7)*(V).z; acc[7][3] += (A7)*(V).w;

__global__ void __launch_bounds__(256) sim_kernel(float* __restrict__ out) {
    const int blk = blockIdx.x;
    const int bi  = blk & (NIT - 1);           // i-tile 0..31
    const int jt  = blk >> 5;                  // j-tile 0..7
    const int ib  = bi * 8;                    // i rows [ib, ib+8)
    const int t   = threadIdx.x;
    const int jq  = t & 7;                     // j float4-group within tile
    const int ks  = t >> 3;                    // k-slice 0..31 (16 k each)
    const int w   = t >> 5;                    // warp 0..7
    const int lane = t & 31;

#if __CUDA_ARCH__ >= 900
    cudaGridDependencySynchronize();
#endif

    __shared__ float4 sc4[8][F4D];             // 16 KB: i-rows
    __shared__ float4 redw[8][8][8];           // 8 KB: [warp][jq][i]
    {
        const float4* src = reinterpret_cast<const float4*>(g_centers + (size_t)ib * FD);
        for (int k = t; k < 8 * F4D; k += 256)
            sc4[k >> 7][k & 127] = __ldcg(src + k);
    }
    __syncthreads();

    const float4* __restrict__ ct = reinterpret_cast<const float4*>(g_centersT);
    const int col = jt * 8 + jq;               // float4 column in CT row

    float acc[8][4];
    #pragma unroll
    for (int i = 0; i < 8; ++i)
        #pragma unroll
        for (int j = 0; j < 4; ++j) acc[i][j] = 0.f;

    const int kb = ks * 16;
    float4 buf[2][4];
    #pragma unroll
    for (int u = 0; u < 4; ++u)
        buf[0][u] = __ldcg(&ct[(size_t)(kb + u) * (NC / 4) + col]);

    #pragma unroll
    for (int ch = 0; ch < 4; ++ch) {
        const int pb = ch & 1;
        if (ch < 3) {
            const int k2 = kb + (ch + 1) * 4;
            #pragma unroll
            for (int u = 0; u < 4; ++u)
                buf[pb ^ 1][u] = __ldcg(&ct[(size_t)(k2 + u) * (NC / 4) + col]);
        }
        const int kf = (kb + ch * 4) >> 2;
        float4 a0 = sc4[0][kf];
        float4 a1 = sc4[1][kf];
        float4 a2 = sc4[2][kf];
        float4 a3 = sc4[3][kf];
        float4 a4 = sc4[4][kf];
        float4 a5 = sc4[5][kf];
        float4 a6 = sc4[6][kf];
        float4 a7 = sc4[7][kf];
        SIM_STEP8(a0.x, a1.x, a2.x, a3.x, a4.x, a5.x, a6.x, a7.x, buf[pb][0]);
        SIM_STEP8(a0.y, a1.y, a2.y, a3.y, a4.y, a5.y, a6.y, a7.y, buf[pb][1]);
        SIM_STEP8(a0.z, a1.z, a2.z, a3.z, a4.z, a5.z, a6.z, a7.z, buf[pb][2]);
        SIM_STEP8(a0.w, a1.w, a2.w, a3.w, a4.w, a5.w, a6.w, a7.w, buf[pb][3]);
    }

    // intra-warp fold: lanes {jq, jq+8, jq+16, jq+24} share a j-group
    #pragma unroll
    for (int i = 0; i < 8; ++i)
        #pragma unroll
        for (int j = 0; j < 4; ++j) {
            acc[i][j] += __shfl_xor_sync(0xffffffffu, acc[i][j], 8);
            acc[i][j] += __shfl_xor_sync(0xffffffffu, acc[i][j], 16);
        }
    if (lane < 8) {
        #pragma unroll
        for (int i = 0; i < 8; ++i)
            redw[w][lane][i] = make_float4(acc[i][0], acc[i][1], acc[i][2], acc[i][3]);
    }
    __syncthreads();

    __shared__ float s_min[8][8];
    if (t < 64) {                              // thread = (i = t>>3, jq2 = t&7)
        const int i   = t >> 3;
        const int jq2 = t & 7;
        float4 s = make_float4(0.f, 0.f, 0.f, 0.f);
        #pragma unroll
        for (int w2 = 0; w2 < 8; ++w2) {
            float4 v = redw[w2][jq2][i];
            s.x += v.x; s.y += v.y; s.z += v.z; s.w += v.w;
        }
        const int ig = ib + i;
        const int jb = jt * 32 + 4 * jq2;
        float m = CUDART_INF_F;
        if (jb + 0 != ig) m = fminf(m, s.x);
        if (jb + 1 != ig) m = fminf(m, s.y);
        if (jb + 2 != ig) m = fminf(m, s.z);
        if (jb + 3 != ig) m = fminf(m, s.w);
        s_min[i][jq2] = m;
    }
    __syncthreads();
    if (t < 8) {
        float m = CUDART_INF_F;
        #pragma unroll
        for (int q = 0; q < 8; ++q) m = fminf(m, s_min[t][q]);
        g_partmin[(size_t)jt * NC + ib + t] = m;
    }

    // fan-in: last block computes sum(1 - min over jt) into out[0]
    __threadfence();
    __shared__ unsigned int s_prev;
    if (t == 0) s_prev = atomicAdd(&g_cnt2, 1u);
    __syncthreads();
    if (s_prev != NBLK2 - 1) return;
    __threadfence();

    float m = __ldcg(&g_partmin[t]);
    #pragma unroll
    for (int jt2 = 1; jt2 < NJT; ++jt2)
        m = fminf(m, __ldcg(&g_partmin[(size_t)jt2 * NC + t]));
    float v = 1.0f - m;

    #pragma unroll
    for (int o = 16; o > 0; o >>= 1)
        v += __shfl_xor_sync(0xffffffffu, v, o);

    __shared__ float sfin[8];
    if ((t & 31) == 0) sfin[t >> 5] = v;
    __syncthreads();
    if (t == 0) {
        float total = 0.f;
        #pragma unroll
        for (int i = 0; i < 8; ++i) total += sfin[i];
        out[0] = total;
        g_cnt2 = 0u;   // reset for next graph replay
    }
}

extern "C" void kernel_launch(void* const* d_in, const int* in_sizes, int n_in,
                              void* d_out, int out_size) {
    const float* feat = (const float*)d_in[0];
    float* out = (float*)d_out;

    centers_kernel<<<NC * RSPLIT, 128>>>(feat);

    cudaLaunchAttribute attr[1];
    attr[0].id = cudaLaunchAttributeProgrammaticStreamSerialization;
    attr[0].val.programmaticStreamSerializationAllowed = 1;

    cudaLaunchConfig_t cfg = {};
    cfg.gridDim  = dim3(NBLK2, 1, 1);
    cfg.blockDim = dim3(256, 1, 1);
    cfg.attrs    = attr;
    cfg.numAttrs = 1;
    cudaLaunchKernelEx(&cfg, sim_kernel, out);
}

// round 14
// speedup vs baseline: 1.0960x; 1.0960x over previous
#include <cuda_runtime.h>
#include <math_constants.h>

#define NFEAT 65536
#define FD    512
#define NC    256
#define RPC   (NFEAT / NC)      // 256 rows per class
#define F4D   (FD / 4)          // 128 float4 per row
#define RSPLIT 8                // row-chunks per class
#define RCHUNK (RPC / RSPLIT)   // 32 rows per chunk
#define NIT    64               // i-tiles (4 rows each)
#define NJT    8                // j-tiles (32 cols each)
#define NBLK2  (NIT * NJT)      // 512 sim blocks

// Scratch (no cudaMalloc allowed)
__device__ float g_partial[RSPLIT * NC * FD];  // 4 MB partial sums
__device__ float g_centers[NC * FD];           // normalized centers [j][k]
__device__ float g_centersT[FD * NC];          // normalized centers [k][j]
__device__ float g_partmin[NJT * NC];          // per-(jtile,row) partial min
__device__ unsigned int g_cnt2;                // sim fan-in counter

// ---------------------------------------------------------------------------
// Kernel 1: partial row-sums. grid = 2048, block = 128. Proven at the
// LTS/HBM ceiling for this pattern (~5.8 TB/s, 72%); do not touch.
// ---------------------------------------------------------------------------
__global__ void __launch_bounds__(128) centers_partial_kernel(const float* __restrict__ feat) {
    const int b = blockIdx.x;
    const int c = b >> 3;
    const int s = b & 7;
    const int t = threadIdx.x;

    const float4* __restrict__ p =
        reinterpret_cast<const float4*>(feat)
        + ((size_t)c * RPC + (size_t)s * RCHUNK) * F4D + t;

    float4 acc = make_float4(0.f, 0.f, 0.f, 0.f);
    #pragma unroll
    for (int r = 0; r < RCHUNK; ++r) {
        float4 v = __ldcs(p + (size_t)r * F4D);
        acc.x += v.x; acc.y += v.y; acc.z += v.z; acc.w += v.w;
    }
    reinterpret_cast<float4*>(g_partial)[((size_t)s * NC + c) * F4D + t] = acc;

#if __CUDA_ARCH__ >= 900
    cudaTriggerProgrammaticLaunchCompletion();
#endif
}

// ---------------------------------------------------------------------------
// Kernel 2: fold partials, mean, L2-norm; write row-major + transposed.
// grid = 256, block = 128. PDL secondary.
// ---------------------------------------------------------------------------
__global__ void __launch_bounds__(128) centers_finalize_kernel() {
#if __CUDA_ARCH__ >= 900
    cudaGridDependencySynchronize();
#endif
    const int c = blockIdx.x;
    const int t = threadIdx.x;

    float4 sum = make_float4(0.f, 0.f, 0.f, 0.f);
    #pragma unroll
    for (int k = 0; k < RSPLIT; ++k) {
        float4 v = reinterpret_cast<const float4*>(g_partial)[((size_t)k * NC + c) * F4D + t];
        sum.x += v.x; sum.y += v.y; sum.z += v.z; sum.w += v.w;
    }
    const float inv = 1.0f / (float)RPC;
    sum.x *= inv; sum.y *= inv; sum.z *= inv; sum.w *= inv;

    float ss = sum.x*sum.x + sum.y*sum.y + sum.z*sum.z + sum.w*sum.w;
    #pragma unroll
    for (int o = 16; o > 0; o >>= 1)
        ss += __shfl_xor_sync(0xffffffffu, ss, o);

    __shared__ float sred[4];
    if ((t & 31) == 0) sred[t >> 5] = ss;
    __syncthreads();
    float total = sred[0] + sred[1] + sred[2] + sred[3];
    float invn = 1.0f / fmaxf(sqrtf(total), 1e-8f);

    float4 o4 = make_float4(sum.x * invn, sum.y * invn, sum.z * invn, sum.w * invn);
    reinterpret_cast<float4*>(g_centers)[(size_t)c * F4D + t] = o4;

    g_centersT[(size_t)(4 * t + 0) * NC + c] = o4.x;
    g_centersT[(size_t)(4 * t + 1) * NC + c] = o4.y;
    g_centersT[(size_t)(4 * t + 2) * NC + c] = o4.z;
    g_centersT[(size_t)(4 * t + 3) * NC + c] = o4.w;

#if __CUDA_ARCH__ >= 900
    cudaTriggerProgrammaticLaunchCompletion();
#endif
}

// ---------------------------------------------------------------------------
// Kernel 3: sim row mins, 4 i-rows x 32 j per block = 512 blocks
// (~3.5 blocks/SM, ~28 warps/SM -> latency actually hidden; R13 showed the
// 256-block version was grid-size-limited at 21% occupancy).
// Thread: jq = t&7 owns float4 j-group (j = 32jt+4jq..+3), ks = t>>3 owns
// k in [16ks, 16ks+16). 4 k-slices sharing a j-group fold intra-warp (shfl).
// Last block: min over 8 j-tiles per row, sum(1 - min) -> out[0].
// ---------------------------------------------------------------------------
#define SIM_STEP4(A0, A1, A2, A3, V)                                         \
    acc[0][0] += (A0)*(V).x; acc[0][1] += (A0)*(V).y;                        \
    acc[0][2] += (A0)*(V).z; acc[0][3] += (A0)*(V).w;                        \
    acc[1][0] += (A1)*(V).x; acc[1][1] += (A1)*(V).y;                        \
    acc[1][2] += (A1)*(V).z; acc[1][3] += (A1)*(V).w;                        \
    acc[2][0] += (A2)*(V).x; acc[2][1] += (A2)*(V).y;                        \
    acc[2][2] += (A2)*(V).z; acc[2][3] += (A2)*(V).w;                        \
    acc[3][0] += (A3)*(V).x; acc[3][1] += (A3)*(V).y;                        \
    acc[3][2] += (A3)*(V).z; acc[3][3] += (A3)*(V).w;

__global__ void __launch_bounds__(256) sim_kernel(float* __restrict__ out) {
    const int blk = blockIdx.x;
    const int bi  = blk & (NIT - 1);           // i-tile 0..63
    const int jt  = blk >> 6;                  // j-tile 0..7
    const int ib  = bi * 4;                    // i rows [ib, ib+4)
    const int t   = threadIdx.x;
    const int jq  = t & 7;                     // j float4-group within tile
    const int ks  = t >> 3;                    // k-slice 0..31 (16 k each)
    const int w   = t >> 5;                    // warp 0..7
    const int lane = t & 31;

#if __CUDA_ARCH__ >= 900
    cudaGridDependencySynchronize();
#endif

    __shared__ float4 sc4[4][F4D];             // 8 KB: i-rows
    __shared__ float4 redw[8][8][4];           // 4 KB: [warp][jq][i]
    {
        const float4* src = reinterpret_cast<const float4*>(g_centers + (size_t)ib * FD);
        #pragma unroll
        for (int k = t; k < 4 * F4D; k += 256)
            sc4[k >> 7][k & 127] = src[k];
    }
    __syncthreads();

    const float4* __restrict__ ct = reinterpret_cast<const float4*>(g_centersT);
    const int col = jt * 8 + jq;               // float4 column in CT row

    float acc[4][4];
    #pragma unroll
    for (int i = 0; i < 4; ++i)
        #pragma unroll
        for (int j = 0; j < 4; ++j) acc[i][j] = 0.f;

    const int kb = ks * 16;
    float4 buf[2][4];
    #pragma unroll
    for (int u = 0; u < 4; ++u)
        buf[0][u] = __ldcg(&ct[(size_t)(kb + u) * (NC / 4) + col]);

    #pragma unroll
    for (int ch = 0; ch < 4; ++ch) {
        const int pb = ch & 1;
        if (ch < 3) {
            const int k2 = kb + (ch + 1) * 4;
            #pragma unroll
            for (int u = 0; u < 4; ++u)
                buf[pb ^ 1][u] = __ldcg(&ct[(size_t)(k2 + u) * (NC / 4) + col]);
        }
        const int kf = (kb + ch * 4) >> 2;
        float4 a0 = sc4[0][kf];
        float4 a1 = sc4[1][kf];
        float4 a2 = sc4[2][kf];
        float4 a3 = sc4[3][kf];
        SIM_STEP4(a0.x, a1.x, a2.x, a3.x, buf[pb][0]);
        SIM_STEP4(a0.y, a1.y, a2.y, a3.y, buf[pb][1]);
        SIM_STEP4(a0.z, a1.z, a2.z, a3.z, buf[pb][2]);
        SIM_STEP4(a0.w, a1.w, a2.w, a3.w, buf[pb][3]);
    }

    // intra-warp fold: lanes {jq, jq+8, jq+16, jq+24} share a j-group
    #pragma unroll
    for (int i = 0; i < 4; ++i)
        #pragma unroll
        for (int j = 0; j < 4; ++j) {
            acc[i][j] += __shfl_xor_sync(0xffffffffu, acc[i][j], 8);
            acc[i][j] += __shfl_xor_sync(0xffffffffu, acc[i][j], 16);
        }
    if (lane < 8) {
        #pragma unroll
        for (int i = 0; i < 4; ++i)
            redw[w][lane][i] = make_float4(acc[i][0], acc[i][1], acc[i][2], acc[i][3]);
    }
    __syncthreads();

    __shared__ float s_min[4][8];
    if (t < 32) {                              // thread = (i = t>>3, jq2 = t&7)
        const int i   = t >> 3;
        const int jq2 = t & 7;
        float4 s = make_float4(0.f, 0.f, 0.f, 0.f);
        #pragma unroll
        for (int w2 = 0; w2 < 8; ++w2) {
            float4 v = redw[w2][jq2][i];
            s.x += v.x; s.y += v.y; s.z += v.z; s.w += v.w;
        }
        const int ig = ib + i;
        const int jb = jt * 32 + 4 * jq2;
        float m = CUDART_INF_F;
        if (jb + 0 != ig) m = fminf(m, s.x);
        if (jb + 1 != ig) m = fminf(m, s.y);
        if (jb + 2 != ig) m = fminf(m, s.z);
        if (jb + 3 != ig) m = fminf(m, s.w);
        s_min[i][jq2] = m;
    }
    __syncthreads();
    if (t < 4) {
        float m = CUDART_INF_F;
        #pragma unroll
        for (int q = 0; q < 8; ++q) m = fminf(m, s_min[t][q]);
        g_partmin[(size_t)jt * NC + ib + t] = m;
    }

    // fan-in: last block computes sum(1 - min over jt) into out[0]
    __threadfence();
    __shared__ unsigned int s_prev;
    if (t == 0) s_prev = atomicAdd(&g_cnt2, 1u);
    __syncthreads();
    if (s_prev != NBLK2 - 1) return;
    __threadfence();

    float m = __ldcg(&g_partmin[t]);
    #pragma unroll
    for (int jt2 = 1; jt2 < NJT; ++jt2)
        m = fminf(m, __ldcg(&g_partmin[(size_t)jt2 * NC + t]));
    float v = 1.0f - m;

    #pragma unroll
    for (int o = 16; o > 0; o >>= 1)
        v += __shfl_xor_sync(0xffffffffu, v, o);

    __shared__ float sfin[8];
    if ((t & 31) == 0) sfin[t >> 5] = v;
    __syncthreads();
    if (t == 0) {
        float total = 0.f;
        #pragma unroll
        for (int i = 0; i < 8; ++i) total += sfin[i];
        out[0] = total;
        g_cnt2 = 0u;   // reset for next graph replay
    }
}

extern "C" void kernel_launch(void* const* d_in, const int* in_sizes, int n_in,
                              void* d_out, int out_size) {
    const float* feat = (const float*)d_in[0];
    float* out = (float*)d_out;

    centers_partial_kernel<<<NC * RSPLIT, 128>>>(feat);

    cudaLaunchAttribute attr[1];
    attr[0].id = cudaLaunchAttributeProgrammaticStreamSerialization;
    attr[0].val.programmaticStreamSerializationAllowed = 1;

    {
        cudaLaunchConfig_t cfg = {};
        cfg.gridDim  = dim3(NC, 1, 1);
        cfg.blockDim = dim3(128, 1, 1);
        cfg.attrs    = attr;
        cfg.numAttrs = 1;
        cudaLaunchKernelEx(&cfg, centers_finalize_kernel);
    }
    {
        cudaLaunchConfig_t cfg = {};
        cfg.gridDim  = dim3(NBLK2, 1, 1);
        cfg.blockDim = dim3(256, 1, 1);
        cfg.attrs    = attr;
        cfg.numAttrs = 1;
        cudaLaunchKernelEx(&cfg, sim_kernel, out);
    }
}